// round 15
// baseline (speedup 1.0000x reference)
#include <cuda_runtime.h>
#include <cuda_fp16.h>
#include <cstdint>
#include <cstddef>

// Problem constants
#define BB   2
#define SS   2048
#define DD   2048
#define HH   16
#define KVHH 4
#define HDD  128
#define GG   4   // H / KVH
#define NQKV 3072   // 2048 q + 512 k + 512 v

// ---------------------------------------------------------------------------
// Scratch (device globals — no allocations allowed)
// ---------------------------------------------------------------------------
__device__ float  g_qkv[BB * SS * NQKV];          // fused QKV fp32 out
__device__ __half g_qh[BB * SS * HH * HDD];       // post-rope fp16
__device__ __half g_kh[BB * SS * KVHH * HDD];
__device__ __half g_vt[BB * KVHH * HDD * SS];     // V^T per head: [b][kh][hd][s]
__device__ __half g_ctx[BB * SS * HH * HDD];
__device__ __half g_hs_h[BB * SS * DD];
__device__ __half g_wqkv_h[NQKV * DD];            // [wq|wk|wv]^T : [N][K]
__device__ __half g_wo_h[DD * DD];

// ---------------------------------------------------------------------------
// helpers
// ---------------------------------------------------------------------------
__device__ __forceinline__ void mma16x8x16(float* c, const uint32_t* a,
                                           const uint32_t* b) {
    asm volatile(
        "mma.sync.aligned.m16n8k16.row.col.f32.f16.f16.f32 "
        "{%0,%1,%2,%3}, {%4,%5,%6,%7}, {%8,%9}, {%0,%1,%2,%3};\n"
        : "+f"(c[0]), "+f"(c[1]), "+f"(c[2]), "+f"(c[3])
        : "r"(a[0]), "r"(a[1]), "r"(a[2]), "r"(a[3]), "r"(b[0]), "r"(b[1]));
}

__device__ __forceinline__ void cp16(uint32_t dst, const void* src) {
    asm volatile("cp.async.cg.shared.global [%0], [%1], 16;\n"
                 :: "r"(dst), "l"(src));
}
__device__ __forceinline__ void cp_commit() {
    asm volatile("cp.async.commit_group;\n");
}
template <int N>
__device__ __forceinline__ void cp_wait() {
    asm volatile("cp.async.wait_group %0;\n" :: "n"(N));
}

// ---------------------------------------------------------------------------
// pre-processing kernels
// ---------------------------------------------------------------------------
__global__ void f2h_kernel(const float4* __restrict__ src,
                           uint2* __restrict__ dst, int n4)
{
    for (int i = blockIdx.x * blockDim.x + threadIdx.x; i < n4;
         i += gridDim.x * blockDim.x) {
        const float4 v = src[i];
        const __half2 lo = __floats2half2_rn(v.x, v.y);
        const __half2 hi = __floats2half2_rn(v.z, v.w);
        uint2 u;
        u.x = *(const uint32_t*)&lo;
        u.y = *(const uint32_t*)&hi;
        dst[i] = u;
    }
}

// All 4 weight transposes in ONE launch. z selects tensor.
__global__ void trans4_kernel(const float* __restrict__ wq,
                              const float* __restrict__ wk,
                              const float* __restrict__ wv,
                              const float* __restrict__ wo,
                              __half* __restrict__ wqkvh,
                              __half* __restrict__ woh)
{
    const int z = blockIdx.z;
    const float* src;
    __half* dst;
    int C;
    if (z == 0)      { src = wq; dst = wqkvh;                           C = DD;  }
    else if (z == 1) { src = wk; dst = wqkvh + (size_t)DD * DD;         C = 512; }
    else if (z == 2) { src = wv; dst = wqkvh + (size_t)(DD + 512) * DD; C = 512; }
    else             { src = wo; dst = woh;                             C = DD;  }
    if (blockIdx.x * 32 >= C) return;

    __shared__ float t[32][33];
    const int c0 = blockIdx.x * 32;
    const int r0 = blockIdx.y * 32;
    const int tx = threadIdx.x, ty = threadIdx.y;
    #pragma unroll
    for (int i = 0; i < 4; i++)
        t[ty + 8 * i][tx] = src[(size_t)(r0 + ty + 8 * i) * C + c0 + tx];
    __syncthreads();
    #pragma unroll
    for (int i = 0; i < 4; i++)
        dst[(size_t)(c0 + ty + 8 * i) * DD + r0 + tx] =
            __float2half(t[tx][ty + 8 * i]);
}

// RoPE for Q and K in ONE launch (vectorized, 4 pairs/thread).
__global__ void rope_all_kernel(const float* __restrict__ x,
                                __half* __restrict__ qh,
                                __half* __restrict__ kh,
                                const float* __restrict__ cosT,
                                const float* __restrict__ sinT)
{
    const int gid = blockIdx.x * blockDim.x + threadIdx.x;
    const int qtot = BB * SS * HH * 16;
    int idx, heads, coff;
    __half* y;
    float scale;
    if (gid < qtot) { idx = gid;        heads = HH;   coff = 0;  y = qh;
                      scale = 0.08838834764831845f; }
    else            { idx = gid - qtot; heads = KVHH; coff = DD; y = kh;
                      scale = 1.0f; }

    const int c4 = (idx & 15) << 2;
    const int h  = (idx >> 4) % heads;
    const int s  = (idx / (16 * heads)) % SS;
    const int b  = idx / (16 * heads * SS);

    const size_t sb = (size_t)(b * SS + s) * NQKV + coff + h * HDD;
    const float4 x1 = *(const float4*)(x + sb + c4);
    const float4 x2 = *(const float4*)(x + sb + c4 + 64);
    const float4 c1 = *(const float4*)(cosT + s * HDD + c4);
    const float4 s1 = *(const float4*)(sinT + s * HDD + c4);
    const float4 c2 = *(const float4*)(cosT + s * HDD + c4 + 64);
    const float4 s2 = *(const float4*)(sinT + s * HDD + c4 + 64);

    const size_t db = (size_t)((b * SS + s) * heads + h) * HDD;
    const __half2 lo0 = __floats2half2_rn((x1.x * c1.x - x2.x * s1.x) * scale,
                                          (x1.y * c1.y - x2.y * s1.y) * scale);
    const __half2 lo1 = __floats2half2_rn((x1.z * c1.z - x2.z * s1.z) * scale,
                                          (x1.w * c1.w - x2.w * s1.w) * scale);
    const __half2 hi0 = __floats2half2_rn((x2.x * c2.x + x1.x * s2.x) * scale,
                                          (x2.y * c2.y + x1.y * s2.y) * scale);
    const __half2 hi1 = __floats2half2_rn((x2.z * c2.z + x1.z * s2.z) * scale,
                                          (x2.w * c2.w + x1.w * s2.w) * scale);
    uint2 u;
    u.x = *(const uint32_t*)&lo0; u.y = *(const uint32_t*)&lo1;
    *(uint2*)(y + db + c4) = u;
    u.x = *(const uint32_t*)&hi0; u.y = *(const uint32_t*)&hi1;
    *(uint2*)(y + db + c4 + 64) = u;
}

// V (in fused qkv, col offset 2560) -> Vt [b][kvh][hd][s] fp16
__global__ void vtrans_kernel(const float* __restrict__ qkv,
                              __half* __restrict__ vt)
{
    __shared__ float t[32][33];
    const int hd0 = blockIdx.x * 32;
    const int s0  = blockIdx.y * 32;
    const int bk  = blockIdx.z;
    const int b   = bk / KVHH;
    const int kh  = bk % KVHH;
    const int tx = threadIdx.x, ty = threadIdx.y;
    #pragma unroll
    for (int i = 0; i < 4; i++)
        t[ty + 8 * i][tx] =
            qkv[(size_t)(b * SS + s0 + ty + 8 * i) * NQKV + 2560 + kh * HDD
                + hd0 + tx];
    __syncthreads();
    #pragma unroll
    for (int i = 0; i < 4; i++)
        vt[((size_t)(b * KVHH + kh) * HDD + hd0 + ty + 8 * i) * SS + s0 + tx] =
            __float2half(t[tx][ty + 8 * i]);
}

// ---------------------------------------------------------------------------
// FP16 tensor-core GEMM (unchanged, at legacy-HMMA issue ceiling).
// ---------------------------------------------------------------------------
#define HG_ASZ   10240
#define HG_BSZ   20480
#define HG_STG   (HG_ASZ + HG_BSZ)
#define HG_SMEM  (4 * HG_STG)

__global__ __launch_bounds__(256, 1) void hgemm_kernel(
    const __half* __restrict__ A, const __half* __restrict__ Bt,
    float* __restrict__ C, int M, int N, int K)
{
    extern __shared__ char gsm[];
    uint32_t sbase;
    asm("{ .reg .u64 t; cvta.to.shared.u64 t, %1; cvt.u32.u64 %0, t; }"
        : "=r"(sbase) : "l"(gsm));

    const int tid  = threadIdx.x;
    const int lane = tid & 31;
    const int warp = tid >> 5;
    const int wm   = (warp >> 2) * 64;
    const int wn   = (warp & 3) * 64;
    const int grp  = lane >> 2;
    const int qid  = lane & 3;
    const int bm   = blockIdx.y * 128;
    const int bn   = blockIdx.x * 256;

    float c[4][8][4];
    #pragma unroll
    for (int mi = 0; mi < 4; mi++)
        #pragma unroll
        for (int ni = 0; ni < 8; ni++)
            #pragma unroll
            for (int r = 0; r < 4; r++) c[mi][ni][r] = 0.f;

    const int T = K / 32;

    auto issue = [&](int st) {
        const int s = st & 3;
        const uint32_t as = sbase + s * HG_STG;
        const uint32_t bs = as + HG_ASZ;
        const int k0 = st * 32;
        #pragma unroll
        for (int i = 0; i < 2; i++) {
            const int ch = tid + i * 256;
            const int r  = ch >> 2;
            const int c8 = (ch & 3) << 3;
            cp16(as + (r * 40 + c8) * 2, A + (size_t)(bm + r) * K + k0 + c8);
        }
        #pragma unroll
        for (int i = 0; i < 4; i++) {
            const int ch = tid + i * 256;
            const int r  = ch >> 2;
            const int c8 = (ch & 3) << 3;
            cp16(bs + (r * 40 + c8) * 2, Bt + (size_t)(bn + r) * K + k0 + c8);
        }
        cp_commit();
    };

    issue(0);
    issue(1);
    issue(2);

    for (int t = 0; t < T; t++) {
        if (t < T - 2)       cp_wait<2>();
        else if (t == T - 2) cp_wait<1>();
        else                 cp_wait<0>();
        __syncthreads();
        if (t + 3 < T) issue(t + 3);

        const uint32_t* As32 = (const uint32_t*)(gsm + (t & 3) * HG_STG);
        const uint32_t* Bs32 = (const uint32_t*)(gsm + (t & 3) * HG_STG + HG_ASZ);
        #pragma unroll
        for (int kk2 = 0; kk2 < 16; kk2 += 8) {
            uint32_t a[4][4], bf[8][2];
            #pragma unroll
            for (int mi = 0; mi < 4; mi++) {
                const int m = wm + mi * 16 + grp;
                a[mi][0] = As32[m * 20 + kk2 + qid];
                a[mi][1] = As32[(m + 8) * 20 + kk2 + qid];
                a[mi][2] = As32[m * 20 + kk2 + qid + 4];
                a[mi][3] = As32[(m + 8) * 20 + kk2 + qid + 4];
            }
            #pragma unroll
            for (int ni = 0; ni < 8; ni++) {
                const int n = wn + ni * 8 + grp;
                bf[ni][0] = Bs32[n * 20 + kk2 + qid];
                bf[ni][1] = Bs32[n * 20 + kk2 + qid + 4];
            }
            #pragma unroll
            for (int mi = 0; mi < 4; mi++)
                #pragma unroll
                for (int ni = 0; ni < 8; ni++)
                    mma16x8x16(c[mi][ni], a[mi], bf[ni]);
        }
        __syncthreads();
    }

    #pragma unroll
    for (int mi = 0; mi < 4; mi++) {
        const int row0 = bm + wm + mi * 16 + grp;
        #pragma unroll
        for (int ni = 0; ni < 8; ni++) {
            const int col = bn + wn + ni * 8 + qid * 2;
            *(float2*)&C[(size_t)row0 * N + col] =
                make_float2(c[mi][ni][0], c[mi][ni][1]);
            *(float2*)&C[(size_t)(row0 + 8) * N + col] =
                make_float2(c[mi][ni][2], c[mi][ni][3]);
        }
    }
}

// ---------------------------------------------------------------------------
// FP16 flash attention (R11 structure + warp-uniform causal MMA pruning).
// BM=128, BN=128, 8 warps. Q/P in registers. Alibi+mask staged via cp.async.
// Diagonal tile: warp w skips score blocks ni>2w+1 and PV steps j>w.
// ---------------------------------------------------------------------------
#define AT_Q    0
#define AT_K    34816                        // 128*136*2
#define AT_KSTG 34816
#define AT_V    104448                       // 128*136*2
#define AT_AL   139264                       // 128*136*4 = 69632
#define AT_MK   208896                       // 128*4 = 512
#define AT_SMEM 209408

__global__ __launch_bounds__(256, 1) void attn_kernel(
    const __half* __restrict__ q, const __half* __restrict__ k,
    const __half* __restrict__ vt, const float* __restrict__ alibi,
    const float* __restrict__ mask, __half* __restrict__ ctx)
{
    extern __shared__ char asm_raw[];
    uint32_t* S32 = (uint32_t*)asm_raw;
    uint32_t sbase;
    asm("{ .reg .u64 t; cvta.to.shared.u64 t, %1; cvt.u32.u64 %0, t; }"
        : "=r"(sbase) : "l"(asm_raw));

    uint32_t* Q32  = S32;                   // stride 68 u32
    uint32_t* K32  = S32 + AT_K / 4;        // 2 stages, stride 68
    uint32_t* Vt32 = S32 + AT_V / 4;        // stride 68
    const float* ALf = (const float*)(asm_raw + AT_AL);   // [128][136] f32
    const float* MKf = (const float*)(asm_raw + AT_MK);   // [128] f32

    const int tid  = threadIdx.x;
    const int lane = tid & 31;
    const int warp = tid >> 5;
    const int grp  = lane >> 2;
    const int qid  = lane & 3;
    const int bxr  = gridDim.x - 1 - blockIdx.x;   // heavy first
    const int bh   = blockIdx.y;
    const int b    = bh / HH;
    const int h    = bh % HH;
    const int kh   = h / GG;
    const int q0   = bxr * 128;
    const int rl   = warp * 16 + grp;

    const int ntiles = bxr + 1;

    auto issue_K = [&](int kv, int buf) {
        #pragma unroll
        for (int i = 0; i < 8; i++) {
            const int ch = tid + i * 256;
            const int r  = ch >> 4;
            const int c8 = (ch & 15) << 3;
            cp16(sbase + AT_K + buf * AT_KSTG + (r * 136 + c8) * 2,
                 k + (size_t)((b * SS + kv + r) * KVHH + kh) * HDD + c8);
        }
    };
    auto issue_VAM = [&](int kv) {
        #pragma unroll
        for (int i = 0; i < 8; i++) {         // V
            const int ch = tid + i * 256;
            const int r  = ch >> 4;
            const int c8 = (ch & 15) << 3;
            cp16(sbase + AT_V + (r * 136 + c8) * 2,
                 vt + ((size_t)(b * KVHH + kh) * HDD + r) * SS + kv + c8);
        }
        #pragma unroll
        for (int i = 0; i < 16; i++) {        // alibi tile
            const int ch = tid + i * 256;
            const int r  = ch >> 5;
            const int c4 = (ch & 31) << 2;
            cp16(sbase + AT_AL + (r * 136 + c4) * 4,
                 alibi + ((size_t)b * SS + q0 + r) * SS + kv + c4);
        }
        if (tid < 32)
            cp16(sbase + AT_MK + tid * 16, mask + b * SS + kv + tid * 4);
    };

    // prologue: G1=[Q,K0], G2=[V0,AL0,M0]
    #pragma unroll
    for (int i = 0; i < 8; i++) {
        const int ch = tid + i * 256;
        const int r  = ch >> 4;
        const int c8 = (ch & 15) << 3;
        cp16(sbase + AT_Q + (r * 136 + c8) * 2,
             q + (size_t)((b * SS + q0 + r) * HH + h) * HDD + c8);
    }
    issue_K(0, 0);
    cp_commit();
    issue_VAM(0);
    cp_commit();

    float o[16][4];
    #pragma unroll
    for (int ni = 0; ni < 16; ni++)
        #pragma unroll
        for (int r = 0; r < 4; r++) o[ni][r] = 0.f;
    float m0 = -1e30f, m1 = -1e30f, l0 = 0.f, l1 = 0.f;

    const int rg0 = q0 + rl;
    const int rg1 = rg0 + 8;

    cp_wait<1>();
    __syncthreads();
    uint32_t qreg[32];
    #pragma unroll
    for (int s8 = 0; s8 < 8; s8++) {
        const int kk2 = s8 * 8;
        qreg[s8 * 4 + 0] = Q32[rl * 68 + kk2 + qid];
        qreg[s8 * 4 + 1] = Q32[(rl + 8) * 68 + kk2 + qid];
        qreg[s8 * 4 + 2] = Q32[rl * 68 + kk2 + qid + 4];
        qreg[s8 * 4 + 3] = Q32[(rl + 8) * 68 + kk2 + qid + 4];
    }

    for (int t = 0; t < ntiles; t++) {
        const int kv0 = t * 128;
        const int pk  = t & 1;
        const bool diag = (t == ntiles - 1);
        // warp-uniform causal limits (full tiles: 16 / 8)
        const int niLim = diag ? (2 * warp + 2) : 16;
        const int jLim  = diag ? (warp + 1) : 8;

        if (t > 0) {
            cp_wait<1>();
            __syncthreads();
        }

        if (t + 1 < ntiles) {
            issue_K(kv0 + 128, (t + 1) & 1);
            cp_commit();
        }

        // ---- scores: 16x128 warp tile (pruned on diag), Q from regs ----
        float sf[16][4];
        #pragma unroll
        for (int ni = 0; ni < 16; ni++)
            #pragma unroll
            for (int r = 0; r < 4; r++) sf[ni][r] = 0.f;

        const uint32_t* Kb = K32 + pk * (AT_KSTG / 4);
        #pragma unroll
        for (int s8 = 0; s8 < 8; s8++) {
            const int kk2 = s8 * 8;
            const uint32_t* a = &qreg[s8 * 4];
            #pragma unroll
            for (int ni = 0; ni < 16; ni++) {
                if (ni < niLim) {
                    const int n = ni * 8 + grp;
                    uint32_t bf[2] = { Kb[n * 68 + kk2 + qid],
                                       Kb[n * 68 + kk2 + qid + 4] };
                    mma16x8x16(sf[ni], a, bf);
                }
            }
        }

        // G_VA(t) done
        if (t + 1 < ntiles) cp_wait<1>();
        else                cp_wait<0>();
        __syncthreads();

        // ---- bias + causal ----
        #pragma unroll
        for (int ni = 0; ni < 16; ni++) {
            if (ni < niLim) {
                const int cl = ni * 8 + 2 * qid;
                const int cg = kv0 + cl;
                const float2 mk = *(const float2*)(MKf + cl);
                const float2 a0 = *(const float2*)(ALf + rl * 136 + cl);
                const float2 a1 = *(const float2*)(ALf + (rl + 8) * 136 + cl);
                sf[ni][0] += a0.x + mk.x;
                sf[ni][1] += a0.y + mk.y;
                sf[ni][2] += a1.x + mk.x;
                sf[ni][3] += a1.y + mk.y;
                if (diag) {
                    if (cg > rg0)     sf[ni][0] = -1e30f;
                    if (cg + 1 > rg0) sf[ni][1] = -1e30f;
                    if (cg > rg1)     sf[ni][2] = -1e30f;
                    if (cg + 1 > rg1) sf[ni][3] = -1e30f;
                }
            } else {
                sf[ni][0] = -1e30f; sf[ni][1] = -1e30f;
                sf[ni][2] = -1e30f; sf[ni][3] = -1e30f;
            }
        }

        // ---- warp-local online softmax; P packed into registers ----
        float mx0 = -1e30f, mx1 = -1e30f;
        #pragma unroll
        for (int ni = 0; ni < 16; ni++) {
            mx0 = fmaxf(mx0, fmaxf(sf[ni][0], sf[ni][1]));
            mx1 = fmaxf(mx1, fmaxf(sf[ni][2], sf[ni][3]));
        }
        mx0 = fmaxf(mx0, __shfl_xor_sync(0xffffffffu, mx0, 1));
        mx0 = fmaxf(mx0, __shfl_xor_sync(0xffffffffu, mx0, 2));
        mx1 = fmaxf(mx1, __shfl_xor_sync(0xffffffffu, mx1, 1));
        mx1 = fmaxf(mx1, __shfl_xor_sync(0xffffffffu, mx1, 2));

        const float nm0 = fmaxf(m0, mx0);
        const float nm1 = fmaxf(m1, mx1);
        const float f0  = __expf(m0 - nm0);
        const float f1  = __expf(m1 - nm1);
        float ls0 = 0.f, ls1 = 0.f;
        uint32_t pr[16][2];
        #pragma unroll
        for (int ni = 0; ni < 16; ni++) {
            if (ni < niLim) {
                const float p0 = __expf(sf[ni][0] - nm0);
                const float p1 = __expf(sf[ni][1] - nm0);
                const float p2 = __expf(sf[ni][2] - nm1);
                const float p3 = __expf(sf[ni][3] - nm1);
                ls0 += p0 + p1;
                ls1 += p2 + p3;
                const __half2 hp0 = __floats2half2_rn(p0, p1);
                const __half2 hp1 = __floats2half2_rn(p2, p3);
                pr[ni][0] = *(const uint32_t*)&hp0;
                pr[ni][1] = *(const uint32_t*)&hp1;
            } else {
                pr[ni][0] = 0u;
                pr[ni][1] = 0u;
            }
        }
        ls0 += __shfl_xor_sync(0xffffffffu, ls0, 1);
        ls0 += __shfl_xor_sync(0xffffffffu, ls0, 2);
        ls1 += __shfl_xor_sync(0xffffffffu, ls1, 1);
        ls1 += __shfl_xor_sync(0xffffffffu, ls1, 2);
        l0 = l0 * f0 + ls0;  m0 = nm0;
        l1 = l1 * f1 + ls1;  m1 = nm1;

        #pragma unroll
        for (int ni = 0; ni < 16; ni++) {
            o[ni][0] *= f0; o[ni][1] *= f0;
            o[ni][2] *= f1; o[ni][3] *= f1;
        }

        // ---- PV: P from registers (pruned on diag) ----
        #pragma unroll
        for (int j = 0; j < 8; j++) {
            if (j < jLim) {
                const int kk2 = j * 8;
                uint32_t a[4] = { pr[2 * j][0], pr[2 * j][1],
                                  pr[2 * j + 1][0], pr[2 * j + 1][1] };
                #pragma unroll
                for (int ni = 0; ni < 16; ni++) {
                    const int n = ni * 8 + grp;        // hd row of Vt
                    uint32_t bf[2] = { Vt32[n * 68 + kk2 + qid],
                                       Vt32[n * 68 + kk2 + qid + 4] };
                    mma16x8x16(o[ni], a, bf);
                }
            }
        }
        __syncthreads();             // all warps done with V(t), AL(t), M(t)

        if (t + 1 < ntiles) {
            issue_VAM(kv0 + 128);
            cp_commit();
        }
    }

    // epilogue
    const float il0 = 1.f / l0;
    const float il1 = 1.f / l1;
    #pragma unroll
    for (int ni = 0; ni < 16; ni++) {
        const int col = ni * 8 + 2 * qid;
        __half* d0 = ctx + (size_t)((b * SS + rg0) * HH + h) * HDD + col;
        __half* d1 = ctx + (size_t)((b * SS + rg1) * HH + h) * HDD + col;
        *(__half2*)d0 = __floats2half2_rn(o[ni][0] * il0, o[ni][1] * il0);
        *(__half2*)d1 = __floats2half2_rn(o[ni][2] * il1, o[ni][3] * il1);
    }
}

// ---------------------------------------------------------------------------
// Launch
// ---------------------------------------------------------------------------
extern "C" void kernel_launch(void* const* d_in, const int* in_sizes, int n_in,
                              void* d_out, int out_size)
{
    const float* hs    = (const float*)d_in[0];
    const float* cosT  = (const float*)d_in[1];
    const float* sinT  = (const float*)d_in[2];
    const float* alibi = (const float*)d_in[3];
    const float* mask  = (const float*)d_in[4];
    const float* wq    = (const float*)d_in[5];
    const float* wk    = (const float*)d_in[6];
    const float* wv    = (const float*)d_in[7];
    const float* wo    = (const float*)d_in[8];
    float* out = (float*)d_out;

    float  *qkv;
    __half *qh, *kh, *vt, *cb, *hsh, *wqkvh, *woh;
    cudaGetSymbolAddress((void**)&qkv,   g_qkv);
    cudaGetSymbolAddress((void**)&qh,    g_qh);
    cudaGetSymbolAddress((void**)&kh,    g_kh);
    cudaGetSymbolAddress((void**)&vt,    g_vt);
    cudaGetSymbolAddress((void**)&cb,    g_ctx);
    cudaGetSymbolAddress((void**)&hsh,   g_hs_h);
    cudaGetSymbolAddress((void**)&wqkvh, g_wqkv_h);
    cudaGetSymbolAddress((void**)&woh,   g_wo_h);

    const int M = BB * SS;   // 4096

    f2h_kernel<<<1024, 256>>>((const float4*)hs, (uint2*)hsh, BB * SS * DD / 4);
    {
        dim3 blk(32, 8);
        trans4_kernel<<<dim3(64, 64, 4), blk>>>(wq, wk, wv, wo, wqkvh, woh);
    }

    cudaFuncSetAttribute(hgemm_kernel,
                         cudaFuncAttributeMaxDynamicSharedMemorySize, HG_SMEM);

    hgemm_kernel<<<dim3(NQKV / 256, M / 128), 256, HG_SMEM>>>(
        hsh, wqkvh, qkv, M, NQKV, DD);

    {
        const int total = BB * SS * (HH + KVHH) * 16;
        rope_all_kernel<<<total / 256, 256>>>(qkv, qh, kh, cosT, sinT);
        dim3 blk(32, 8);
        vtrans_kernel<<<dim3(HDD / 32, SS / 32, BB * KVHH), blk>>>(qkv, vt);
    }

    {
        cudaFuncSetAttribute(attn_kernel,
                             cudaFuncAttributeMaxDynamicSharedMemorySize,
                             AT_SMEM);
        dim3 ga(SS / 128, BB * HH);
        attn_kernel<<<ga, 256, AT_SMEM>>>(qh, kh, vt, alibi, mask, cb);
    }

    hgemm_kernel<<<dim3(DD / 256, M / 128), 256, HG_SMEM>>>(
        cb, woh, out, M, DD, DD);
}

// round 17
// speedup vs baseline: 1.0464x; 1.0464x over previous
#include <cuda_runtime.h>
#include <cuda_fp16.h>
#include <cstdint>
#include <cstddef>

// Problem constants
#define BB   2
#define SS   2048
#define DD   2048
#define HH   16
#define KVHH 4
#define HDD  128
#define GG   4   // H / KVH
#define NQKV 3072   // 2048 q + 512 k + 512 v

// ---------------------------------------------------------------------------
// Scratch (device globals — no allocations allowed)
// ---------------------------------------------------------------------------
__device__ float  g_qkv[BB * SS * NQKV];          // fused QKV fp32 out
__device__ __half g_qh[BB * SS * HH * HDD];       // post-rope fp16
__device__ __half g_kh[BB * SS * KVHH * HDD];
__device__ __half g_vt[BB * KVHH * HDD * SS];     // V^T per head: [b][kh][hd][s]
__device__ __half g_ctx[BB * SS * HH * HDD];
__device__ __half g_hs_h[BB * SS * DD];
__device__ __half g_wqkv_h[NQKV * DD];            // [wq|wk|wv]^T : [N][K]
__device__ __half g_wo_h[DD * DD];

// ---------------------------------------------------------------------------
// helpers
// ---------------------------------------------------------------------------
__device__ __forceinline__ void mma16x8x16(float* c, const uint32_t* a,
                                           const uint32_t* b) {
    asm volatile(
        "mma.sync.aligned.m16n8k16.row.col.f32.f16.f16.f32 "
        "{%0,%1,%2,%3}, {%4,%5,%6,%7}, {%8,%9}, {%0,%1,%2,%3};\n"
        : "+f"(c[0]), "+f"(c[1]), "+f"(c[2]), "+f"(c[3])
        : "r"(a[0]), "r"(a[1]), "r"(a[2]), "r"(a[3]), "r"(b[0]), "r"(b[1]));
}

__device__ __forceinline__ void cp16(uint32_t dst, const void* src) {
    asm volatile("cp.async.cg.shared.global [%0], [%1], 16;\n"
                 :: "r"(dst), "l"(src));
}
__device__ __forceinline__ void cp_commit() {
    asm volatile("cp.async.commit_group;\n");
}
template <int N>
__device__ __forceinline__ void cp_wait() {
    asm volatile("cp.async.wait_group %0;\n" :: "n"(N));
}

// ---------------------------------------------------------------------------
// pre-processing kernels
// ---------------------------------------------------------------------------
__global__ void f2h_kernel(const float4* __restrict__ src,
                           uint2* __restrict__ dst, int n4)
{
    for (int i = blockIdx.x * blockDim.x + threadIdx.x; i < n4;
         i += gridDim.x * blockDim.x) {
        const float4 v = src[i];
        const __half2 lo = __floats2half2_rn(v.x, v.y);
        const __half2 hi = __floats2half2_rn(v.z, v.w);
        uint2 u;
        u.x = *(const uint32_t*)&lo;
        u.y = *(const uint32_t*)&hi;
        dst[i] = u;
    }
}

// All 4 weight transposes in ONE launch. z selects tensor.
__global__ void trans4_kernel(const float* __restrict__ wq,
                              const float* __restrict__ wk,
                              const float* __restrict__ wv,
                              const float* __restrict__ wo,
                              __half* __restrict__ wqkvh,
                              __half* __restrict__ woh)
{
    const int z = blockIdx.z;
    const float* src;
    __half* dst;
    int C;
    if (z == 0)      { src = wq; dst = wqkvh;                           C = DD;  }
    else if (z == 1) { src = wk; dst = wqkvh + (size_t)DD * DD;         C = 512; }
    else if (z == 2) { src = wv; dst = wqkvh + (size_t)(DD + 512) * DD; C = 512; }
    else             { src = wo; dst = woh;                             C = DD;  }
    if (blockIdx.x * 32 >= C) return;

    __shared__ float t[32][33];
    const int c0 = blockIdx.x * 32;
    const int r0 = blockIdx.y * 32;
    const int tx = threadIdx.x, ty = threadIdx.y;
    #pragma unroll
    for (int i = 0; i < 4; i++)
        t[ty + 8 * i][tx] = src[(size_t)(r0 + ty + 8 * i) * C + c0 + tx];
    __syncthreads();
    #pragma unroll
    for (int i = 0; i < 4; i++)
        dst[(size_t)(c0 + ty + 8 * i) * DD + r0 + tx] =
            __float2half(t[tx][ty + 8 * i]);
}

// RoPE for Q and K in ONE launch (vectorized, 4 pairs/thread).
__global__ void rope_all_kernel(const float* __restrict__ x,
                                __half* __restrict__ qh,
                                __half* __restrict__ kh,
                                const float* __restrict__ cosT,
                                const float* __restrict__ sinT)
{
    const int gid = blockIdx.x * blockDim.x + threadIdx.x;
    const int qtot = BB * SS * HH * 16;
    int idx, heads, coff;
    __half* y;
    float scale;
    if (gid < qtot) { idx = gid;        heads = HH;   coff = 0;  y = qh;
                      scale = 0.08838834764831845f; }
    else            { idx = gid - qtot; heads = KVHH; coff = DD; y = kh;
                      scale = 1.0f; }

    const int c4 = (idx & 15) << 2;
    const int h  = (idx >> 4) % heads;
    const int s  = (idx / (16 * heads)) % SS;
    const int b  = idx / (16 * heads * SS);

    const size_t sb = (size_t)(b * SS + s) * NQKV + coff + h * HDD;
    const float4 x1 = *(const float4*)(x + sb + c4);
    const float4 x2 = *(const float4*)(x + sb + c4 + 64);
    const float4 c1 = *(const float4*)(cosT + s * HDD + c4);
    const float4 s1 = *(const float4*)(sinT + s * HDD + c4);
    const float4 c2 = *(const float4*)(cosT + s * HDD + c4 + 64);
    const float4 s2 = *(const float4*)(sinT + s * HDD + c4 + 64);

    const size_t db = (size_t)((b * SS + s) * heads + h) * HDD;
    const __half2 lo0 = __floats2half2_rn((x1.x * c1.x - x2.x * s1.x) * scale,
                                          (x1.y * c1.y - x2.y * s1.y) * scale);
    const __half2 lo1 = __floats2half2_rn((x1.z * c1.z - x2.z * s1.z) * scale,
                                          (x1.w * c1.w - x2.w * s1.w) * scale);
    const __half2 hi0 = __floats2half2_rn((x2.x * c2.x + x1.x * s2.x) * scale,
                                          (x2.y * c2.y + x1.y * s2.y) * scale);
    const __half2 hi1 = __floats2half2_rn((x2.z * c2.z + x1.z * s2.z) * scale,
                                          (x2.w * c2.w + x1.w * s2.w) * scale);
    uint2 u;
    u.x = *(const uint32_t*)&lo0; u.y = *(const uint32_t*)&lo1;
    *(uint2*)(y + db + c4) = u;
    u.x = *(const uint32_t*)&hi0; u.y = *(const uint32_t*)&hi1;
    *(uint2*)(y + db + c4 + 64) = u;
}

// V (in fused qkv, col offset 2560) -> Vt [b][kvh][hd][s] fp16
__global__ void vtrans_kernel(const float* __restrict__ qkv,
                              __half* __restrict__ vt)
{
    __shared__ float t[32][33];
    const int hd0 = blockIdx.x * 32;
    const int s0  = blockIdx.y * 32;
    const int bk  = blockIdx.z;
    const int b   = bk / KVHH;
    const int kh  = bk % KVHH;
    const int tx = threadIdx.x, ty = threadIdx.y;
    #pragma unroll
    for (int i = 0; i < 4; i++)
        t[ty + 8 * i][tx] =
            qkv[(size_t)(b * SS + s0 + ty + 8 * i) * NQKV + 2560 + kh * HDD
                + hd0 + tx];
    __syncthreads();
    #pragma unroll
    for (int i = 0; i < 4; i++)
        vt[((size_t)(b * KVHH + kh) * HDD + hd0 + ty + 8 * i) * SS + s0 + tx] =
            __float2half(t[tx][ty + 8 * i]);
}

// ---------------------------------------------------------------------------
// FP16 tensor-core GEMM (unchanged, at legacy-HMMA issue ceiling).
// ---------------------------------------------------------------------------
#define HG_ASZ   10240
#define HG_BSZ   20480
#define HG_STG   (HG_ASZ + HG_BSZ)
#define HG_SMEM  (4 * HG_STG)

__global__ __launch_bounds__(256, 1) void hgemm_kernel(
    const __half* __restrict__ A, const __half* __restrict__ Bt,
    float* __restrict__ C, int M, int N, int K)
{
    extern __shared__ char gsm[];
    uint32_t sbase;
    asm("{ .reg .u64 t; cvta.to.shared.u64 t, %1; cvt.u32.u64 %0, t; }"
        : "=r"(sbase) : "l"(gsm));

    const int tid  = threadIdx.x;
    const int lane = tid & 31;
    const int warp = tid >> 5;
    const int wm   = (warp >> 2) * 64;
    const int wn   = (warp & 3) * 64;
    const int grp  = lane >> 2;
    const int qid  = lane & 3;
    const int bm   = blockIdx.y * 128;
    const int bn   = blockIdx.x * 256;

    float c[4][8][4];
    #pragma unroll
    for (int mi = 0; mi < 4; mi++)
        #pragma unroll
        for (int ni = 0; ni < 8; ni++)
            #pragma unroll
            for (int r = 0; r < 4; r++) c[mi][ni][r] = 0.f;

    const int T = K / 32;

    auto issue = [&](int st) {
        const int s = st & 3;
        const uint32_t as = sbase + s * HG_STG;
        const uint32_t bs = as + HG_ASZ;
        const int k0 = st * 32;
        #pragma unroll
        for (int i = 0; i < 2; i++) {
            const int ch = tid + i * 256;
            const int r  = ch >> 2;
            const int c8 = (ch & 3) << 3;
            cp16(as + (r * 40 + c8) * 2, A + (size_t)(bm + r) * K + k0 + c8);
        }
        #pragma unroll
        for (int i = 0; i < 4; i++) {
            const int ch = tid + i * 256;
            const int r  = ch >> 2;
            const int c8 = (ch & 3) << 3;
            cp16(bs + (r * 40 + c8) * 2, Bt + (size_t)(bn + r) * K + k0 + c8);
        }
        cp_commit();
    };

    issue(0);
    issue(1);
    issue(2);

    for (int t = 0; t < T; t++) {
        if (t < T - 2)       cp_wait<2>();
        else if (t == T - 2) cp_wait<1>();
        else                 cp_wait<0>();
        __syncthreads();
        if (t + 3 < T) issue(t + 3);

        const uint32_t* As32 = (const uint32_t*)(gsm + (t & 3) * HG_STG);
        const uint32_t* Bs32 = (const uint32_t*)(gsm + (t & 3) * HG_STG + HG_ASZ);
        #pragma unroll
        for (int kk2 = 0; kk2 < 16; kk2 += 8) {
            uint32_t a[4][4], bf[8][2];
            #pragma unroll
            for (int mi = 0; mi < 4; mi++) {
                const int m = wm + mi * 16 + grp;
                a[mi][0] = As32[m * 20 + kk2 + qid];
                a[mi][1] = As32[(m + 8) * 20 + kk2 + qid];
                a[mi][2] = As32[m * 20 + kk2 + qid + 4];
                a[mi][3] = As32[(m + 8) * 20 + kk2 + qid + 4];
            }
            #pragma unroll
            for (int ni = 0; ni < 8; ni++) {
                const int n = wn + ni * 8 + grp;
                bf[ni][0] = Bs32[n * 20 + kk2 + qid];
                bf[ni][1] = Bs32[n * 20 + kk2 + qid + 4];
            }
            #pragma unroll
            for (int mi = 0; mi < 4; mi++)
                #pragma unroll
                for (int ni = 0; ni < 8; ni++)
                    mma16x8x16(c[mi][ni], a[mi], bf[ni]);
        }
        __syncthreads();
    }

    #pragma unroll
    for (int mi = 0; mi < 4; mi++) {
        const int row0 = bm + wm + mi * 16 + grp;
        #pragma unroll
        for (int ni = 0; ni < 8; ni++) {
            const int col = bn + wn + ni * 8 + qid * 2;
            *(float2*)&C[(size_t)row0 * N + col] =
                make_float2(c[mi][ni][0], c[mi][ni][1]);
            *(float2*)&C[(size_t)(row0 + 8) * N + col] =
                make_float2(c[mi][ni][2], c[mi][ni][3]);
        }
    }
}

// ---------------------------------------------------------------------------
// FP16 flash attention. BM=128, BN=128, 8 warps. Q/P in registers.
// Diagonal tile PEELED out of the main loop: full-tile body is branch-free
// (no causal checks at all); the peeled diag block carries causal masking
// + warp-uniform MMA pruning.
// ---------------------------------------------------------------------------
#define AT_Q    0
#define AT_K    34816                        // 128*136*2
#define AT_KSTG 34816
#define AT_V    104448                       // 128*136*2
#define AT_AL   139264                       // 128*136*4 = 69632
#define AT_MK   208896                       // 128*4 = 512
#define AT_SMEM 209408

__global__ __launch_bounds__(256, 1) void attn_kernel(
    const __half* __restrict__ q, const __half* __restrict__ k,
    const __half* __restrict__ vt, const float* __restrict__ alibi,
    const float* __restrict__ mask, __half* __restrict__ ctx)
{
    extern __shared__ char asm_raw[];
    uint32_t* S32 = (uint32_t*)asm_raw;
    uint32_t sbase;
    asm("{ .reg .u64 t; cvta.to.shared.u64 t, %1; cvt.u32.u64 %0, t; }"
        : "=r"(sbase) : "l"(asm_raw));

    uint32_t* Q32  = S32;                   // stride 68 u32
    uint32_t* K32  = S32 + AT_K / 4;        // 2 stages, stride 68
    uint32_t* Vt32 = S32 + AT_V / 4;        // stride 68
    const float* ALf = (const float*)(asm_raw + AT_AL);   // [128][136] f32
    const float* MKf = (const float*)(asm_raw + AT_MK);   // [128] f32

    const int tid  = threadIdx.x;
    const int lane = tid & 31;
    const int warp = tid >> 5;
    const int grp  = lane >> 2;
    const int qid  = lane & 3;
    const int bxr  = gridDim.x - 1 - blockIdx.x;   // heavy first
    const int bh   = blockIdx.y;
    const int b    = bh / HH;
    const int h    = bh % HH;
    const int kh   = h / GG;
    const int q0   = bxr * 128;
    const int rl   = warp * 16 + grp;

    const int ntiles = bxr + 1;

    auto issue_K = [&](int kv, int buf) {
        #pragma unroll
        for (int i = 0; i < 8; i++) {
            const int ch = tid + i * 256;
            const int r  = ch >> 4;
            const int c8 = (ch & 15) << 3;
            cp16(sbase + AT_K + buf * AT_KSTG + (r * 136 + c8) * 2,
                 k + (size_t)((b * SS + kv + r) * KVHH + kh) * HDD + c8);
        }
    };
    auto issue_VAM = [&](int kv) {
        #pragma unroll
        for (int i = 0; i < 8; i++) {         // V
            const int ch = tid + i * 256;
            const int r  = ch >> 4;
            const int c8 = (ch & 15) << 3;
            cp16(sbase + AT_V + (r * 136 + c8) * 2,
                 vt + ((size_t)(b * KVHH + kh) * HDD + r) * SS + kv + c8);
        }
        #pragma unroll
        for (int i = 0; i < 16; i++) {        // alibi tile
            const int ch = tid + i * 256;
            const int r  = ch >> 5;
            const int c4 = (ch & 31) << 2;
            cp16(sbase + AT_AL + (r * 136 + c4) * 4,
                 alibi + ((size_t)b * SS + q0 + r) * SS + kv + c4);
        }
        if (tid < 32)
            cp16(sbase + AT_MK + tid * 16, mask + b * SS + kv + tid * 4);
    };

    // prologue: G1=[Q,K0], G2=[V0,AL0,M0]
    #pragma unroll
    for (int i = 0; i < 8; i++) {
        const int ch = tid + i * 256;
        const int r  = ch >> 4;
        const int c8 = (ch & 15) << 3;
        cp16(sbase + AT_Q + (r * 136 + c8) * 2,
             q + (size_t)((b * SS + q0 + r) * HH + h) * HDD + c8);
    }
    issue_K(0, 0);
    cp_commit();
    issue_VAM(0);
    cp_commit();

    float o[16][4];
    #pragma unroll
    for (int ni = 0; ni < 16; ni++)
        #pragma unroll
        for (int r = 0; r < 4; r++) o[ni][r] = 0.f;
    float m0 = -1e30f, m1 = -1e30f, l0 = 0.f, l1 = 0.f;

    const int rg0 = q0 + rl;
    const int rg1 = rg0 + 8;

    cp_wait<1>();
    __syncthreads();
    uint32_t qreg[32];
    #pragma unroll
    for (int s8 = 0; s8 < 8; s8++) {
        const int kk2 = s8 * 8;
        qreg[s8 * 4 + 0] = Q32[rl * 68 + kk2 + qid];
        qreg[s8 * 4 + 1] = Q32[(rl + 8) * 68 + kk2 + qid];
        qreg[s8 * 4 + 2] = Q32[rl * 68 + kk2 + qid + 4];
        qreg[s8 * 4 + 3] = Q32[(rl + 8) * 68 + kk2 + qid + 4];
    }

    // ======== full (off-diagonal) tiles: branch-free body ========
    for (int t = 0; t < ntiles - 1; t++) {
        const int kv0 = t * 128;
        const int pk  = t & 1;

        if (t > 0) {
            cp_wait<1>();
            __syncthreads();
        }

        // prefetch K(t+1) — always valid here
        issue_K(kv0 + 128, (t + 1) & 1);
        cp_commit();

        // ---- scores: 16x128 warp tile ----
        float sf[16][4];
        #pragma unroll
        for (int ni = 0; ni < 16; ni++)
            #pragma unroll
            for (int r = 0; r < 4; r++) sf[ni][r] = 0.f;

        const uint32_t* Kb = K32 + pk * (AT_KSTG / 4);
        #pragma unroll
        for (int s8 = 0; s8 < 8; s8++) {
            const int kk2 = s8 * 8;
            const uint32_t* a = &qreg[s8 * 4];
            #pragma unroll
            for (int ni = 0; ni < 16; ni++) {
                const int n = ni * 8 + grp;
                uint32_t bf[2] = { Kb[n * 68 + kk2 + qid],
                                   Kb[n * 68 + kk2 + qid + 4] };
                mma16x8x16(sf[ni], a, bf);
            }
        }

        cp_wait<1>();           // G_VA(t) done; K(t+1) still pending
        __syncthreads();

        // ---- bias (no causal here: kv0+127 < q0) ----
        #pragma unroll
        for (int ni = 0; ni < 16; ni++) {
            const int cl = ni * 8 + 2 * qid;
            const float2 mk = *(const float2*)(MKf + cl);
            const float2 a0 = *(const float2*)(ALf + rl * 136 + cl);
            const float2 a1 = *(const float2*)(ALf + (rl + 8) * 136 + cl);
            sf[ni][0] += a0.x + mk.x;
            sf[ni][1] += a0.y + mk.y;
            sf[ni][2] += a1.x + mk.x;
            sf[ni][3] += a1.y + mk.y;
        }

        // ---- warp-local online softmax; P into registers ----
        float mx0 = -1e30f, mx1 = -1e30f;
        #pragma unroll
        for (int ni = 0; ni < 16; ni++) {
            mx0 = fmaxf(mx0, fmaxf(sf[ni][0], sf[ni][1]));
            mx1 = fmaxf(mx1, fmaxf(sf[ni][2], sf[ni][3]));
        }
        mx0 = fmaxf(mx0, __shfl_xor_sync(0xffffffffu, mx0, 1));
        mx0 = fmaxf(mx0, __shfl_xor_sync(0xffffffffu, mx0, 2));
        mx1 = fmaxf(mx1, __shfl_xor_sync(0xffffffffu, mx1, 1));
        mx1 = fmaxf(mx1, __shfl_xor_sync(0xffffffffu, mx1, 2));

        const float nm0 = fmaxf(m0, mx0);
        const float nm1 = fmaxf(m1, mx1);
        const float f0  = __expf(m0 - nm0);
        const float f1  = __expf(m1 - nm1);
        float ls0 = 0.f, ls1 = 0.f;
        uint32_t pr[16][2];
        #pragma unroll
        for (int ni = 0; ni < 16; ni++) {
            const float p0 = __expf(sf[ni][0] - nm0);
            const float p1 = __expf(sf[ni][1] - nm0);
            const float p2 = __expf(sf[ni][2] - nm1);
            const float p3 = __expf(sf[ni][3] - nm1);
            ls0 += p0 + p1;
            ls1 += p2 + p3;
            const __half2 hp0 = __floats2half2_rn(p0, p1);
            const __half2 hp1 = __floats2half2_rn(p2, p3);
            pr[ni][0] = *(const uint32_t*)&hp0;
            pr[ni][1] = *(const uint32_t*)&hp1;
        }
        ls0 += __shfl_xor_sync(0xffffffffu, ls0, 1);
        ls0 += __shfl_xor_sync(0xffffffffu, ls0, 2);
        ls1 += __shfl_xor_sync(0xffffffffu, ls1, 1);
        ls1 += __shfl_xor_sync(0xffffffffu, ls1, 2);
        l0 = l0 * f0 + ls0;  m0 = nm0;
        l1 = l1 * f1 + ls1;  m1 = nm1;

        #pragma unroll
        for (int ni = 0; ni < 16; ni++) {
            o[ni][0] *= f0; o[ni][1] *= f0;
            o[ni][2] *= f1; o[ni][3] *= f1;
        }

        // ---- PV ----
        #pragma unroll
        for (int j = 0; j < 8; j++) {
            const int kk2 = j * 8;
            uint32_t a[4] = { pr[2 * j][0], pr[2 * j][1],
                              pr[2 * j + 1][0], pr[2 * j + 1][1] };
            #pragma unroll
            for (int ni = 0; ni < 16; ni++) {
                const int n = ni * 8 + grp;
                uint32_t bf[2] = { Vt32[n * 68 + kk2 + qid],
                                   Vt32[n * 68 + kk2 + qid + 4] };
                mma16x8x16(o[ni], a, bf);
            }
        }
        __syncthreads();

        issue_VAM(kv0 + 128);
        cp_commit();
    }

    // ======== peeled diagonal tile (t = ntiles-1) ========
    {
        const int t   = ntiles - 1;
        const int kv0 = t * 128;
        const int pk  = t & 1;
        const int niLim = 2 * warp + 2;   // warp-uniform causal limits
        const int jLim  = warp + 1;

        if (t > 0) {
            cp_wait<1>();
            __syncthreads();
        }

        float sf[16][4];
        #pragma unroll
        for (int ni = 0; ni < 16; ni++)
            #pragma unroll
            for (int r = 0; r < 4; r++) sf[ni][r] = 0.f;

        const uint32_t* Kb = K32 + pk * (AT_KSTG / 4);
        #pragma unroll
        for (int s8 = 0; s8 < 8; s8++) {
            const int kk2 = s8 * 8;
            const uint32_t* a = &qreg[s8 * 4];
            #pragma unroll
            for (int ni = 0; ni < 16; ni++) {
                if (ni < niLim) {
                    const int n = ni * 8 + grp;
                    uint32_t bf[2] = { Kb[n * 68 + kk2 + qid],
                                       Kb[n * 68 + kk2 + qid + 4] };
                    mma16x8x16(sf[ni], a, bf);
                }
            }
        }

        cp_wait<0>();
        __syncthreads();

        #pragma unroll
        for (int ni = 0; ni < 16; ni++) {
            if (ni < niLim) {
                const int cl = ni * 8 + 2 * qid;
                const int cg = kv0 + cl;
                const float2 mk = *(const float2*)(MKf + cl);
                const float2 a0 = *(const float2*)(ALf + rl * 136 + cl);
                const float2 a1 = *(const float2*)(ALf + (rl + 8) * 136 + cl);
                sf[ni][0] += a0.x + mk.x;
                sf[ni][1] += a0.y + mk.y;
                sf[ni][2] += a1.x + mk.x;
                sf[ni][3] += a1.y + mk.y;
                if (cg > rg0)     sf[ni][0] = -1e30f;
                if (cg + 1 > rg0) sf[ni][1] = -1e30f;
                if (cg > rg1)     sf[ni][2] = -1e30f;
                if (cg + 1 > rg1) sf[ni][3] = -1e30f;
            } else {
                sf[ni][0] = -1e30f; sf[ni][1] = -1e30f;
                sf[ni][2] = -1e30f; sf[ni][3] = -1e30f;
            }
        }

        float mx0 = -1e30f, mx1 = -1e30f;
        #pragma unroll
        for (int ni = 0; ni < 16; ni++) {
            mx0 = fmaxf(mx0, fmaxf(sf[ni][0], sf[ni][1]));
            mx1 = fmaxf(mx1, fmaxf(sf[ni][2], sf[ni][3]));
        }
        mx0 = fmaxf(mx0, __shfl_xor_sync(0xffffffffu, mx0, 1));
        mx0 = fmaxf(mx0, __shfl_xor_sync(0xffffffffu, mx0, 2));
        mx1 = fmaxf(mx1, __shfl_xor_sync(0xffffffffu, mx1, 1));
        mx1 = fmaxf(mx1, __shfl_xor_sync(0xffffffffu, mx1, 2));

        const float nm0 = fmaxf(m0, mx0);
        const float nm1 = fmaxf(m1, mx1);
        const float f0  = __expf(m0 - nm0);
        const float f1  = __expf(m1 - nm1);
        float ls0 = 0.f, ls1 = 0.f;
        uint32_t pr[16][2];
        #pragma unroll
        for (int ni = 0; ni < 16; ni++) {
            if (ni < niLim) {
                const float p0 = __expf(sf[ni][0] - nm0);
                const float p1 = __expf(sf[ni][1] - nm0);
                const float p2 = __expf(sf[ni][2] - nm1);
                const float p3 = __expf(sf[ni][3] - nm1);
                ls0 += p0 + p1;
                ls1 += p2 + p3;
                const __half2 hp0 = __floats2half2_rn(p0, p1);
                const __half2 hp1 = __floats2half2_rn(p2, p3);
                pr[ni][0] = *(const uint32_t*)&hp0;
                pr[ni][1] = *(const uint32_t*)&hp1;
            } else {
                pr[ni][0] = 0u;
                pr[ni][1] = 0u;
            }
        }
        ls0 += __shfl_xor_sync(0xffffffffu, ls0, 1);
        ls0 += __shfl_xor_sync(0xffffffffu, ls0, 2);
        ls1 += __shfl_xor_sync(0xffffffffu, ls1, 1);
        ls1 += __shfl_xor_sync(0xffffffffu, ls1, 2);
        l0 = l0 * f0 + ls0;  m0 = nm0;
        l1 = l1 * f1 + ls1;  m1 = nm1;

        #pragma unroll
        for (int ni = 0; ni < 16; ni++) {
            o[ni][0] *= f0; o[ni][1] *= f0;
            o[ni][2] *= f1; o[ni][3] *= f1;
        }

        #pragma unroll
        for (int j = 0; j < 8; j++) {
            if (j < jLim) {
                const int kk2 = j * 8;
                uint32_t a[4] = { pr[2 * j][0], pr[2 * j][1],
                                  pr[2 * j + 1][0], pr[2 * j + 1][1] };
                #pragma unroll
                for (int ni = 0; ni < 16; ni++) {
                    const int n = ni * 8 + grp;
                    uint32_t bf[2] = { Vt32[n * 68 + kk2 + qid],
                                       Vt32[n * 68 + kk2 + qid + 4] };
                    mma16x8x16(o[ni], a, bf);
                }
            }
        }
    }

    // epilogue
    const float il0 = 1.f / l0;
    const float il1 = 1.f / l1;
    #pragma unroll
    for (int ni = 0; ni < 16; ni++) {
        const int col = ni * 8 + 2 * qid;
        __half* d0 = ctx + (size_t)((b * SS + rg0) * HH + h) * HDD + col;
        __half* d1 = ctx + (size_t)((b * SS + rg1) * HH + h) * HDD + col;
        *(__half2*)d0 = __floats2half2_rn(o[ni][0] * il0, o[ni][1] * il0);
        *(__half2*)d1 = __floats2half2_rn(o[ni][2] * il1, o[ni][3] * il1);
    }
}

// ---------------------------------------------------------------------------
// Launch
// ---------------------------------------------------------------------------
extern "C" void kernel_launch(void* const* d_in, const int* in_sizes, int n_in,
                              void* d_out, int out_size)
{
    const float* hs    = (const float*)d_in[0];
    const float* cosT  = (const float*)d_in[1];
    const float* sinT  = (const float*)d_in[2];
    const float* alibi = (const float*)d_in[3];
    const float* mask  = (const float*)d_in[4];
    const float* wq    = (const float*)d_in[5];
    const float* wk    = (const float*)d_in[6];
    const float* wv    = (const float*)d_in[7];
    const float* wo    = (const float*)d_in[8];
    float* out = (float*)d_out;

    float  *qkv;
    __half *qh, *kh, *vt, *cb, *hsh, *wqkvh, *woh;
    cudaGetSymbolAddress((void**)&qkv,   g_qkv);
    cudaGetSymbolAddress((void**)&qh,    g_qh);
    cudaGetSymbolAddress((void**)&kh,    g_kh);
    cudaGetSymbolAddress((void**)&vt,    g_vt);
    cudaGetSymbolAddress((void**)&cb,    g_ctx);
    cudaGetSymbolAddress((void**)&hsh,   g_hs_h);
    cudaGetSymbolAddress((void**)&wqkvh, g_wqkv_h);
    cudaGetSymbolAddress((void**)&woh,   g_wo_h);

    const int M = BB * SS;   // 4096

    f2h_kernel<<<1024, 256>>>((const float4*)hs, (uint2*)hsh, BB * SS * DD / 4);
    {
        dim3 blk(32, 8);
        trans4_kernel<<<dim3(64, 64, 4), blk>>>(wq, wk, wv, wo, wqkvh, woh);
    }

    cudaFuncSetAttribute(hgemm_kernel,
                         cudaFuncAttributeMaxDynamicSharedMemorySize, HG_SMEM);

    hgemm_kernel<<<dim3(NQKV / 256, M / 128), 256, HG_SMEM>>>(
        hsh, wqkvh, qkv, M, NQKV, DD);

    {
        const int total = BB * SS * (HH + KVHH) * 16;
        rope_all_kernel<<<total / 256, 256>>>(qkv, qh, kh, cosT, sinT);
        dim3 blk(32, 8);
        vtrans_kernel<<<dim3(HDD / 32, SS / 32, BB * KVHH), blk>>>(qkv, vt);
    }

    {
        cudaFuncSetAttribute(attn_kernel,
                             cudaFuncAttributeMaxDynamicSharedMemorySize,
                             AT_SMEM);
        dim3 ga(SS / 128, BB * HH);
        attn_kernel<<<ga, 256, AT_SMEM>>>(qh, kh, vt, alibi, mask, cb);
    }

    hgemm_kernel<<<dim3(DD / 256, M / 128), 256, HG_SMEM>>>(
        cb, woh, out, M, DD, DD);
}